// round 11
// baseline (speedup 1.0000x reference)
#include <cuda_runtime.h>
#include <cuda_bf16.h>
#include <cstdint>

// VectorQuantizer R10: bf16 mma two-sweep filter, PER-ROW sweep-2 gate
// (fixes the R9 crash: rows whose min exceeded the global threshold were
// never rescored, leaving a sentinel index that drove an OOB gather),
// 32 rows/warp, codebook resident in smem, exact fp32 recheck.

#define NUM_CODES 1024
#define DIM       64
#define HW        1024
#define N_VEC     32768
#define N_TOTAL   2097152
#define TPB       256          // 8 warps, 256 vectors per CTA
#define NBLOCKS   128
#define EPS2      1.5e-3f      // >= 2x worst-case bf16 score-error bound
#define INF       3.402823466e38f
#define ZPAD      65           // z row stride (f32): conflict-free scalar LDS

// smem layout (bytes)
#define OFF_CB    0            // 1024 codes x 4 ksteps x 32 x 8B = 131072
#define OFF_Z     131072       // 256 rows x 65 f32               = 66560
#define OFF_CN    197632       // 1024 f32                        = 4096
#define OFF_BEST  201728       // 256 i32                         = 1024
#define OFF_RED   202752       // 256 f32                         = 1024
#define SMEM_TOTAL 203776

__device__ float        g_cnorm[NUM_CODES];
__device__ float        g_partial[NBLOCKS];
__device__ __align__(16) uint2 g_bfrag[NUM_CODES * 16];  // 128 KB bf16 B frags
__device__ unsigned int g_done;

__device__ __forceinline__ uint32_t pk_bf2(float lo, float hi) {
    uint32_t u;
    asm("cvt.rn.bf16x2.f32 %0, %1, %2;" : "=r"(u) : "f"(hi), "f"(lo));
    return u;
}
__device__ __forceinline__ void mma_bf16(float* d, const uint32_t* a,
                                         uint32_t b0, uint32_t b1) {
    asm("mma.sync.aligned.m16n8k16.row.col.f32.bf16.bf16.f32 "
        "{%0,%1,%2,%3}, {%4,%5,%6,%7}, {%8,%9}, {%0,%1,%2,%3};"
        : "+f"(d[0]), "+f"(d[1]), "+f"(d[2]), "+f"(d[3])
        : "r"(a[0]), "r"(a[1]), "r"(a[2]), "r"(a[3]), "r"(b0), "r"(b1));
}

// exact fp32 score, byte-identical sequence to the round-2 passing kernel
__device__ __forceinline__ float exact_score(const float* __restrict__ cb, int k,
                                             const float* zrow, float zn, float cn) {
    const float4* row = (const float4*)(cb + (size_t)k * DIM);
    float d = 0.0f;
#pragma unroll
    for (int i = 0; i < 16; i++) {
        float4 a = row[i];
        d = fmaf(a.x, zrow[4 * i + 0], d);
        d = fmaf(a.y, zrow[4 * i + 1], d);
        d = fmaf(a.z, zrow[4 * i + 2], d);
        d = fmaf(a.w, zrow[4 * i + 3], d);
    }
    return __fadd_rn(__fsub_rn(zn, __fmul_rn(2.0f, d)), cn);
}

// ---------------------------------------------------------------------------
// Prep: warp per code — cn + 16 uint2 B-fragment slots (R8-validated layout).
// ---------------------------------------------------------------------------
__global__ void prep_kernel(const float* __restrict__ cb) {
    int k = (blockIdx.x * blockDim.x + threadIdx.x) >> 5;
    int l = threadIdx.x & 31;
    if (k >= NUM_CODES) return;
    const float* row = cb + (size_t)k * DIM;
    float2 v = *(const float2*)(row + 2 * l);
    float cn = fmaf(v.x, v.x, v.y * v.y);
#pragma unroll
    for (int off = 16; off; off >>= 1)
        cn += __shfl_xor_sync(0xFFFFFFFFu, cn, off);
    if (l == 0) g_cnorm[k] = cn;

    if (l < 16) {
        int kk = l >> 2, t = l & 3;
        int g = k >> 3, n = k & 7;
        int d0 = 16 * kk + 2 * t;
        uint2 val;
        val.x = pk_bf2(row[d0 + 0], row[d0 + 1]);
        val.y = pk_bf2(row[d0 + 8], row[d0 + 9]);
        g_bfrag[(g * 4 + kk) * 32 + n * 4 + t] = val;
    }
}

// ---------------------------------------------------------------------------
// Main
// ---------------------------------------------------------------------------
__global__ void __launch_bounds__(TPB, 1)
vq_main_kernel(const float* __restrict__ z,
               const float* __restrict__ cb,
               float* __restrict__ out,
               float* __restrict__ loss_out) {
    extern __shared__ __align__(16) unsigned char smem[];
    const uint2* s_cb  = (const uint2*)(smem + OFF_CB);
    float*       s_z   = (float*)(smem + OFF_Z);
    float*       s_cn  = (float*)(smem + OFF_CN);
    int*         s_best= (int*)(smem + OFF_BEST);
    float*       s_red = (float*)(smem + OFF_RED);

    const int tid  = threadIdx.x;
    const int w    = tid >> 5, lane = tid & 31;
    const int gid  = lane >> 2, tig = lane & 3;

    // Stage fragment codebook (32 uint4/thread) + cn + z (1 vector/thread).
    {
        const uint4* src = (const uint4*)g_bfrag;
        uint4*       dst = (uint4*)(smem + OFF_CB);
#pragma unroll
        for (int i = 0; i < 32; i++) dst[i * TPB + tid] = src[i * TPB + tid];
    }
#pragma unroll
    for (int i = 0; i < 4; i++) s_cn[tid + i * TPB] = g_cnorm[tid + i * TPB];
    {
        int nz = blockIdx.x * 256 + tid;
        const float* zsrc = z + ((size_t)(nz >> 10) << 16) + (nz & (HW - 1));
        float* zdst = s_z + tid * ZPAD;
#pragma unroll
        for (int c = 0; c < DIM; c++) zdst[c] = zsrc[(size_t)c << 10];
    }
    __syncthreads();

    // Rows: r0=w*32+gid, r0+8 (tile0); r0+16, r0+24 (tile1).
    const int r0 = w * 32 + gid;
    const float* zr0 = s_z + (r0 +  0) * ZPAD;
    const float* zr1 = s_z + (r0 +  8) * ZPAD;
    const float* zr2 = s_z + (r0 + 16) * ZPAD;
    const float* zr3 = s_z + (r0 + 24) * ZPAD;

    // A fragments (R8-validated mapping), values -2z in bf16.
    uint32_t af0[4][4], af1[4][4];
#pragma unroll
    for (int kk = 0; kk < 4; kk++) {
        int c0 = 16 * kk + 2 * tig;
        af0[kk][0] = pk_bf2(-2.0f * zr0[c0],     -2.0f * zr0[c0 + 1]);
        af0[kk][1] = pk_bf2(-2.0f * zr1[c0],     -2.0f * zr1[c0 + 1]);
        af0[kk][2] = pk_bf2(-2.0f * zr0[c0 + 8], -2.0f * zr0[c0 + 9]);
        af0[kk][3] = pk_bf2(-2.0f * zr1[c0 + 8], -2.0f * zr1[c0 + 9]);
        af1[kk][0] = pk_bf2(-2.0f * zr2[c0],     -2.0f * zr2[c0 + 1]);
        af1[kk][1] = pk_bf2(-2.0f * zr3[c0],     -2.0f * zr3[c0 + 1]);
        af1[kk][2] = pk_bf2(-2.0f * zr2[c0 + 8], -2.0f * zr2[c0 + 9]);
        af1[kk][3] = pk_bf2(-2.0f * zr3[c0 + 8], -2.0f * zr3[c0 + 9]);
    }

    // ---------------- Sweep 1: row minima only ----------------
    float rm0 = INF, rm1 = INF, rm2 = INF, rm3 = INF;
#pragma unroll 2
    for (int g = 0; g < 128; g++) {
        float d[4] = {0.f, 0.f, 0.f, 0.f}, e[4] = {0.f, 0.f, 0.f, 0.f};
#pragma unroll
        for (int kk = 0; kk < 4; kk++) {
            uint2 bb = s_cb[(g * 4 + kk) * 32 + lane];
            mma_bf16(d, af0[kk], bb.x, bb.y);
            mma_bf16(e, af1[kk], bb.x, bb.y);
        }
        float2 cn2 = *(const float2*)&s_cn[g * 8 + 2 * tig];
        rm0 = fminf(rm0, fminf(d[0] + cn2.x, d[1] + cn2.y));
        rm1 = fminf(rm1, fminf(d[2] + cn2.x, d[3] + cn2.y));
        rm2 = fminf(rm2, fminf(e[0] + cn2.x, e[1] + cn2.y));
        rm3 = fminf(rm3, fminf(e[2] + cn2.x, e[3] + cn2.y));
    }
    // Merge row minima across the 4 tig lanes (xor flips tig bits only).
#pragma unroll
    for (int dlt = 1; dlt < 4; dlt <<= 1) {
        rm0 = fminf(rm0, __shfl_xor_sync(0xFFFFFFFFu, rm0, dlt));
        rm1 = fminf(rm1, __shfl_xor_sync(0xFFFFFFFFu, rm1, dlt));
        rm2 = fminf(rm2, __shfl_xor_sync(0xFFFFFFFFu, rm2, dlt));
        rm3 = fminf(rm3, __shfl_xor_sync(0xFFFFFFFFu, rm3, dlt));
    }
    const float th0 = rm0 + EPS2, th1 = rm1 + EPS2;
    const float th2 = rm2 + EPS2, th3 = rm3 + EPS2;

    // zn per row, reference sequential order (same bits as R2 passer).
    float zn0 = 0.f, zn1 = 0.f, zn2 = 0.f, zn3 = 0.f;
#pragma unroll
    for (int c = 0; c < DIM; c++) zn0 = fmaf(zr0[c], zr0[c], zn0);
#pragma unroll
    for (int c = 0; c < DIM; c++) zn1 = fmaf(zr1[c], zr1[c], zn1);
#pragma unroll
    for (int c = 0; c < DIM; c++) zn2 = fmaf(zr2[c], zr2[c], zn2);
#pragma unroll
    for (int c = 0; c < DIM; c++) zn3 = fmaf(zr3[c], zr3[c], zn3);

    // ---------------- Sweep 2: PER-ROW gated rescore vs FINAL thresholds ---
    float b0 = INF, b1 = INF, b2 = INF, b3 = INF;
    int   k0 = 0x7FFFFFFF, k1 = 0x7FFFFFFF, k2 = 0x7FFFFFFF, k3 = 0x7FFFFFFF;

#pragma unroll 2
    for (int g = 0; g < 128; g++) {
        float d[4] = {0.f, 0.f, 0.f, 0.f}, e[4] = {0.f, 0.f, 0.f, 0.f};
#pragma unroll
        for (int kk = 0; kk < 4; kk++) {
            uint2 bb = s_cb[(g * 4 + kk) * 32 + lane];
            mma_bf16(d, af0[kk], bb.x, bb.y);
            mma_bf16(e, af1[kk], bb.x, bb.y);
        }
        float2 cn2 = *(const float2*)&s_cn[g * 8 + 2 * tig];
        float s0 = d[0] + cn2.x, s1 = d[1] + cn2.y;
        float s2 = d[2] + cn2.x, s3 = d[3] + cn2.y;
        float s4 = e[0] + cn2.x, s5 = e[1] + cn2.y;
        float s6 = e[2] + cn2.x, s7 = e[3] + cn2.y;
        // Per-row gate: each row compared against ITS OWN threshold.
        bool hit = (fminf(s0, s1) < th0) | (fminf(s2, s3) < th1) |
                   (fminf(s4, s5) < th2) | (fminf(s6, s7) < th3);
        if (hit) {                           // rare
            int kb = g * 8 + 2 * tig;
            if (s0 < th0) { float x = exact_score(cb, kb + 0, zr0, zn0, s_cn[kb + 0]);
                            if (x < b0) { b0 = x; k0 = kb + 0; } }
            if (s1 < th0) { float x = exact_score(cb, kb + 1, zr0, zn0, s_cn[kb + 1]);
                            if (x < b0) { b0 = x; k0 = kb + 1; } }
            if (s2 < th1) { float x = exact_score(cb, kb + 0, zr1, zn1, s_cn[kb + 0]);
                            if (x < b1) { b1 = x; k1 = kb + 0; } }
            if (s3 < th1) { float x = exact_score(cb, kb + 1, zr1, zn1, s_cn[kb + 1]);
                            if (x < b1) { b1 = x; k1 = kb + 1; } }
            if (s4 < th2) { float x = exact_score(cb, kb + 0, zr2, zn2, s_cn[kb + 0]);
                            if (x < b2) { b2 = x; k2 = kb + 0; } }
            if (s5 < th2) { float x = exact_score(cb, kb + 1, zr2, zn2, s_cn[kb + 1]);
                            if (x < b2) { b2 = x; k2 = kb + 1; } }
            if (s6 < th3) { float x = exact_score(cb, kb + 0, zr3, zn3, s_cn[kb + 0]);
                            if (x < b3) { b3 = x; k3 = kb + 0; } }
            if (s7 < th3) { float x = exact_score(cb, kb + 1, zr3, zn3, s_cn[kb + 1]);
                            if (x < b3) { b3 = x; k3 = kb + 1; } }
        }
    }
    __syncwarp();

    // Merge (best, k) per row across tig lanes; exact ties -> smaller k.
#pragma unroll
    for (int dlt = 1; dlt < 4; dlt <<= 1) {
        float ob; int ok;
        ob = __shfl_xor_sync(0xFFFFFFFFu, b0, dlt);
        ok = __shfl_xor_sync(0xFFFFFFFFu, k0, dlt);
        if (ob < b0 || (ob == b0 && ok < k0)) { b0 = ob; k0 = ok; }
        ob = __shfl_xor_sync(0xFFFFFFFFu, b1, dlt);
        ok = __shfl_xor_sync(0xFFFFFFFFu, k1, dlt);
        if (ob < b1 || (ob == b1 && ok < k1)) { b1 = ob; k1 = ok; }
        ob = __shfl_xor_sync(0xFFFFFFFFu, b2, dlt);
        ok = __shfl_xor_sync(0xFFFFFFFFu, k2, dlt);
        if (ob < b2 || (ob == b2 && ok < k2)) { b2 = ob; k2 = ok; }
        ob = __shfl_xor_sync(0xFFFFFFFFu, b3, dlt);
        ok = __shfl_xor_sync(0xFFFFFFFFu, k3, dlt);
        if (ob < b3 || (ob == b3 && ok < k3)) { b3 = ob; k3 = ok; }
    }
    if (tig == 0) {
        s_best[r0 +  0] = k0;
        s_best[r0 +  8] = k1;
        s_best[r0 + 16] = k2;
        s_best[r0 + 24] = k3;
    }
    __syncthreads();

    // Epilogue: thread per vector, 64 dims (R2-identical rounding & order).
    const int nv = blockIdx.x * 256 + tid;
    int bk = s_best[tid];
    if ((unsigned)bk >= NUM_CODES) bk = 0;   // defensive: never OOB
    const float* crow = cb + (size_t)bk * DIM;
    const float* zrow = s_z + tid * ZPAD;
    float* op = out + ((size_t)(nv >> 10) << 16) + (nv & (HW - 1));
    float lsum = 0.0f;
#pragma unroll
    for (int c = 0; c < DIM; c++) {
        float q = crow[c];
        float zv = zrow[c];
        float dd = __fsub_rn(q, zv);
        lsum = fmaf(dd, dd, lsum);
        op[(size_t)c << 10] = __fadd_rn(zv, dd);
    }

    // Deterministic block loss reduction.
    __syncthreads();
    s_red[tid] = lsum;
    __syncthreads();
#pragma unroll
    for (int st = TPB / 2; st > 0; st >>= 1) {
        if (tid < st) s_red[tid] += s_red[tid + st];
        __syncthreads();
    }
    if (tid == 0) g_partial[blockIdx.x] = s_red[0];

    // Fused finale: last CTA reduces all partials in fixed order.
    if (loss_out) {
        __shared__ unsigned int s_rank;
        if (tid == 0) {
            __threadfence();
            s_rank = atomicAdd(&g_done, 1u);
        }
        __syncthreads();
        if (s_rank == NBLOCKS - 1) {
            __threadfence();
            s_red[tid] = (tid < NBLOCKS) ? g_partial[tid] : 0.0f;
            __syncthreads();
#pragma unroll
            for (int st = TPB / 2; st > 0; st >>= 1) {
                if (tid < st) s_red[tid] += s_red[tid + st];
                __syncthreads();
            }
            if (tid == 0) {
                loss_out[0] = s_red[0] * (1.25f / (float)N_TOTAL);
                g_done = 0;   // reset for graph replay
            }
        }
    }
}

// ---------------------------------------------------------------------------
extern "C" void kernel_launch(void* const* d_in, const int* in_sizes, int n_in,
                              void* d_out, int out_size) {
    const float* z  = (const float*)d_in[0];
    const float* cb = (const float*)d_in[1];
    float* out = (float*)d_out;
    float* loss_out = (out_size > N_TOTAL) ? (out + (out_size - 1)) : nullptr;

    cudaFuncSetAttribute(vq_main_kernel,
                         cudaFuncAttributeMaxDynamicSharedMemorySize, SMEM_TOTAL);

    prep_kernel<<<NUM_CODES / 8, 256>>>(cb);
    vq_main_kernel<<<NBLOCKS, TPB, SMEM_TOTAL>>>(z, cb, out, loss_out);
}

// round 12
// speedup vs baseline: 1.8123x; 1.8123x over previous
#include <cuda_runtime.h>
#include <cuda_bf16.h>
#include <cstdint>

// VectorQuantizer R11: R8's validated 16-rows/warp bf16 mma shape +
// two-sweep filter (sweep1 row-min -> FINAL threshold, sweep2 gated rescore)
// + paired-kstep uint4 B fragments (2 LDS.128/group). Exact fp32 recheck
// byte-identical to the R2 passer.

#define NUM_CODES 1024
#define DIM       64
#define HW        1024
#define N_VEC     32768
#define N_TOTAL   2097152
#define TPB       512          // 16 warps, 256 vectors per CTA
#define NBLOCKS   128
#define EPS2      1.5e-3f      // >= 2x worst-case bf16 score-error bound
#define INF       3.402823466e38f
#define ZPAD      65           // z row stride (f32): conflict-free scalar LDS

// smem layout (bytes)
#define OFF_CB    0            // 1024 codes x 8 uint4 = 131072
#define OFF_Z     131072       // 256 rows x 65 f32    = 66560
#define OFF_CN    197632       // 1024 f32             = 4096
#define OFF_BEST  201728       // 256 i32              = 1024
#define OFF_RED   202752       // 512 f32              = 2048
#define SMEM_TOTAL 204800

__device__ float        g_cnorm[NUM_CODES];
__device__ float        g_partial[NBLOCKS];
__device__ __align__(16) uint4 g_bfrag[NUM_CODES * 8];  // 128 KB bf16 B frags
__device__ unsigned int g_done;

__device__ __forceinline__ uint32_t pk_bf2(float lo, float hi) {
    uint32_t u;
    asm("cvt.rn.bf16x2.f32 %0, %1, %2;" : "=r"(u) : "f"(hi), "f"(lo));
    return u;
}
__device__ __forceinline__ void mma_bf16(float* d, const uint32_t* a,
                                         uint32_t b0, uint32_t b1) {
    asm("mma.sync.aligned.m16n8k16.row.col.f32.bf16.bf16.f32 "
        "{%0,%1,%2,%3}, {%4,%5,%6,%7}, {%8,%9}, {%0,%1,%2,%3};"
        : "+f"(d[0]), "+f"(d[1]), "+f"(d[2]), "+f"(d[3])
        : "r"(a[0]), "r"(a[1]), "r"(a[2]), "r"(a[3]), "r"(b0), "r"(b1));
}

// exact fp32 score, byte-identical sequence to the round-2 passing kernel
__device__ __forceinline__ float exact_score(const float* __restrict__ cb, int k,
                                             const float* zrow, float zn, float cn) {
    const float4* row = (const float4*)(cb + (size_t)k * DIM);
    float d = 0.0f;
#pragma unroll
    for (int i = 0; i < 16; i++) {
        float4 a = row[i];
        d = fmaf(a.x, zrow[4 * i + 0], d);
        d = fmaf(a.y, zrow[4 * i + 1], d);
        d = fmaf(a.z, zrow[4 * i + 2], d);
        d = fmaf(a.w, zrow[4 * i + 3], d);
    }
    return __fadd_rn(__fsub_rn(zn, __fmul_rn(2.0f, d)), cn);
}

// ---------------------------------------------------------------------------
// Prep: warp per code — cn + 8 paired-kstep uint4 B-fragment slots.
// Slot (g*2 + h)*32 + n*4 + t  (g=k>>3, n=k&7, h in {0,1}, t in {0..3}):
//   .x/.y = b0/b1 of kstep 2h, .z/.w = b0/b1 of kstep 2h+1
//   b0 = bf16x2(c[16kk+2t], c[16kk+2t+1]), b1 = bf16x2(c[16kk+2t+8], +9)
// ---------------------------------------------------------------------------
__global__ void prep_kernel(const float* __restrict__ cb) {
    int k = (blockIdx.x * blockDim.x + threadIdx.x) >> 5;
    int l = threadIdx.x & 31;
    if (k >= NUM_CODES) return;
    const float* row = cb + (size_t)k * DIM;
    float2 v = *(const float2*)(row + 2 * l);
    float cn = fmaf(v.x, v.x, v.y * v.y);
#pragma unroll
    for (int off = 16; off; off >>= 1)
        cn += __shfl_xor_sync(0xFFFFFFFFu, cn, off);
    if (l == 0) g_cnorm[k] = cn;

    if (l < 8) {
        int h = l >> 2, t = l & 3;
        int g = k >> 3, n = k & 7;
        int kkA = 2 * h, kkB = 2 * h + 1;
        uint4 val;
        val.x = pk_bf2(row[16 * kkA + 2 * t],     row[16 * kkA + 2 * t + 1]);
        val.y = pk_bf2(row[16 * kkA + 2 * t + 8], row[16 * kkA + 2 * t + 9]);
        val.z = pk_bf2(row[16 * kkB + 2 * t],     row[16 * kkB + 2 * t + 1]);
        val.w = pk_bf2(row[16 * kkB + 2 * t + 8], row[16 * kkB + 2 * t + 9]);
        g_bfrag[(g * 2 + h) * 32 + n * 4 + t] = val;
    }
}

// ---------------------------------------------------------------------------
// Main
// ---------------------------------------------------------------------------
__global__ void __launch_bounds__(TPB, 1)
vq_main_kernel(const float* __restrict__ z,
               const float* __restrict__ cb,
               float* __restrict__ out,
               float* __restrict__ loss_out) {
    extern __shared__ __align__(16) unsigned char smem[];
    const uint4* s_cb  = (const uint4*)(smem + OFF_CB);
    float*       s_z   = (float*)(smem + OFF_Z);
    float*       s_cn  = (float*)(smem + OFF_CN);
    int*         s_best= (int*)(smem + OFF_BEST);
    float*       s_red = (float*)(smem + OFF_RED);

    const int tid  = threadIdx.x;
    const int w    = tid >> 5, lane = tid & 31;
    const int gid  = lane >> 2, tig = lane & 3;

    // Stage fragment codebook (16 uint4/thread) + cn + z (2 threads/vector).
    {
        const uint4* src = (const uint4*)g_bfrag;
        uint4*       dst = (uint4*)(smem + OFF_CB);
#pragma unroll
        for (int i = 0; i < 16; i++) dst[i * TPB + tid] = src[i * TPB + tid];
    }
    s_cn[tid] = g_cnorm[tid];
    s_cn[tid + TPB] = g_cnorm[tid + TPB];
    {
        int vz = tid >> 1, hf = tid & 1;
        int nz = blockIdx.x * 256 + vz;
        const float* zsrc = z + ((size_t)(nz >> 10) << 16) + (nz & (HW - 1));
        float* zdst = s_z + vz * ZPAD;
#pragma unroll
        for (int i = 0; i < 32; i++) {
            int c = hf * 32 + i;
            zdst[c] = zsrc[(size_t)c << 10];
        }
    }
    __syncthreads();

    // Rows: rA = w*16+gid, rB = rA+8.
    const int rA = w * 16 + gid;
    const float* zrA = s_z + rA * ZPAD;
    const float* zrB = s_z + (rA + 8) * ZPAD;

    // A fragments (R8-validated mapping), values -2z in bf16.
    uint32_t afr[4][4];
#pragma unroll
    for (int kk = 0; kk < 4; kk++) {
        int c0 = 16 * kk + 2 * tig;
        afr[kk][0] = pk_bf2(-2.0f * zrA[c0],     -2.0f * zrA[c0 + 1]);
        afr[kk][1] = pk_bf2(-2.0f * zrB[c0],     -2.0f * zrB[c0 + 1]);
        afr[kk][2] = pk_bf2(-2.0f * zrA[c0 + 8], -2.0f * zrA[c0 + 9]);
        afr[kk][3] = pk_bf2(-2.0f * zrB[c0 + 8], -2.0f * zrB[c0 + 9]);
    }

    // ---------------- Sweep 1: row minima only ----------------
    float rmA = INF, rmB = INF;
#pragma unroll 4
    for (int g = 0; g < 128; g++) {
        float d[4] = {0.f, 0.f, 0.f, 0.f};
        uint4 p0 = s_cb[(g * 2 + 0) * 32 + lane];
        mma_bf16(d, afr[0], p0.x, p0.y);
        mma_bf16(d, afr[1], p0.z, p0.w);
        uint4 p1 = s_cb[(g * 2 + 1) * 32 + lane];
        mma_bf16(d, afr[2], p1.x, p1.y);
        mma_bf16(d, afr[3], p1.z, p1.w);
        float2 cn2 = *(const float2*)&s_cn[g * 8 + 2 * tig];
        rmA = fminf(rmA, fminf(d[0] + cn2.x, d[1] + cn2.y));
        rmB = fminf(rmB, fminf(d[2] + cn2.x, d[3] + cn2.y));
    }
    // Merge row minima across the 4 tig lanes.
#pragma unroll
    for (int dlt = 1; dlt < 4; dlt <<= 1) {
        rmA = fminf(rmA, __shfl_xor_sync(0xFFFFFFFFu, rmA, dlt));
        rmB = fminf(rmB, __shfl_xor_sync(0xFFFFFFFFu, rmB, dlt));
    }
    const float thA = rmA + EPS2, thB = rmB + EPS2;

    // zn per row, reference sequential order (same bits as R2 passer).
    float znA = 0.f, znB = 0.f;
#pragma unroll
    for (int c = 0; c < DIM; c++) znA = fmaf(zrA[c], zrA[c], znA);
#pragma unroll
    for (int c = 0; c < DIM; c++) znB = fmaf(zrB[c], zrB[c], znB);

    // -------- Sweep 2: PER-ROW gated rescore vs FINAL thresholds --------
    float bA = INF, bB = INF;
    int   kA = 0, kB = 0;
#pragma unroll 2
    for (int g = 0; g < 128; g++) {
        float d[4] = {0.f, 0.f, 0.f, 0.f};
        uint4 p0 = s_cb[(g * 2 + 0) * 32 + lane];
        mma_bf16(d, afr[0], p0.x, p0.y);
        mma_bf16(d, afr[1], p0.z, p0.w);
        uint4 p1 = s_cb[(g * 2 + 1) * 32 + lane];
        mma_bf16(d, afr[2], p1.x, p1.y);
        mma_bf16(d, afr[3], p1.z, p1.w);
        float2 cn2 = *(const float2*)&s_cn[g * 8 + 2 * tig];
        float s0 = d[0] + cn2.x, s1 = d[1] + cn2.y;
        float s2 = d[2] + cn2.x, s3 = d[3] + cn2.y;
        // Per-row gate (each row vs ITS OWN final threshold).
        if ((fminf(s0, s1) < thA) | (fminf(s2, s3) < thB)) {   // rare
            int kb = g * 8 + 2 * tig;
            if (s0 < thA) { float x = exact_score(cb, kb + 0, zrA, znA, s_cn[kb + 0]);
                            if (x < bA) { bA = x; kA = kb + 0; } }
            if (s1 < thA) { float x = exact_score(cb, kb + 1, zrA, znA, s_cn[kb + 1]);
                            if (x < bA) { bA = x; kA = kb + 1; } }
            if (s2 < thB) { float x = exact_score(cb, kb + 0, zrB, znB, s_cn[kb + 0]);
                            if (x < bB) { bB = x; kB = kb + 0; } }
            if (s3 < thB) { float x = exact_score(cb, kb + 1, zrB, znB, s_cn[kb + 1]);
                            if (x < bB) { bB = x; kB = kb + 1; } }
        }
    }
    __syncwarp();

    // Merge (best, k) per row across the 4 tig lanes; ties -> smaller k.
#pragma unroll
    for (int dlt = 1; dlt < 4; dlt <<= 1) {
        float ob; int ok;
        ob = __shfl_xor_sync(0xFFFFFFFFu, bA, dlt);
        ok = __shfl_xor_sync(0xFFFFFFFFu, kA, dlt);
        if (ob < bA || (ob == bA && ok < kA)) { bA = ob; kA = ok; }
        ob = __shfl_xor_sync(0xFFFFFFFFu, bB, dlt);
        ok = __shfl_xor_sync(0xFFFFFFFFu, kB, dlt);
        if (ob < bB || (ob == bB && ok < kB)) { bB = ob; kB = ok; }
    }
    if (tig == 0) {
        s_best[rA]     = kA;
        s_best[rA + 8] = kB;
    }
    __syncthreads();

    // Epilogue: 2 threads/vector, 32 dims each (R2-identical rounding).
    const int vz = tid >> 1, hf = tid & 1;
    const int nv = blockIdx.x * 256 + vz;
    int bk = s_best[vz];
    if ((unsigned)bk >= NUM_CODES) bk = 0;   // defensive: never OOB
    const float* crow = cb + (size_t)bk * DIM;
    const float* zrow = s_z + vz * ZPAD;
    float* op = out + ((size_t)(nv >> 10) << 16) + (nv & (HW - 1));
    float lsum = 0.0f;
#pragma unroll
    for (int i = 0; i < 32; i++) {
        int c = hf * 32 + i;
        float q = crow[c];
        float zv = zrow[c];
        float dd = __fsub_rn(q, zv);
        lsum = fmaf(dd, dd, lsum);
        op[(size_t)c << 10] = __fadd_rn(zv, dd);
    }

    // Deterministic block loss reduction.
    __syncthreads();
    s_red[tid] = lsum;
    __syncthreads();
#pragma unroll
    for (int st = TPB / 2; st > 0; st >>= 1) {
        if (tid < st) s_red[tid] += s_red[tid + st];
        __syncthreads();
    }
    if (tid == 0) g_partial[blockIdx.x] = s_red[0];

    // Fused finale: last CTA reduces all partials in fixed order.
    if (loss_out) {
        __shared__ unsigned int s_rank;
        if (tid == 0) {
            __threadfence();
            s_rank = atomicAdd(&g_done, 1u);
        }
        __syncthreads();
        if (s_rank == NBLOCKS - 1) {
            __threadfence();
            s_red[tid] = (tid < NBLOCKS) ? g_partial[tid] : 0.0f;
            __syncthreads();
#pragma unroll
            for (int st = TPB / 2; st > 0; st >>= 1) {
                if (tid < st) s_red[tid] += s_red[tid + st];
                __syncthreads();
            }
            if (tid == 0) {
                loss_out[0] = s_red[0] * (1.25f / (float)N_TOTAL);
                g_done = 0;   // reset for graph replay
            }
        }
    }
}

// ---------------------------------------------------------------------------
extern "C" void kernel_launch(void* const* d_in, const int* in_sizes, int n_in,
                              void* d_out, int out_size) {
    const float* z  = (const float*)d_in[0];
    const float* cb = (const float*)d_in[1];
    float* out = (float*)d_out;
    float* loss_out = (out_size > N_TOTAL) ? (out + (out_size - 1)) : nullptr;

    cudaFuncSetAttribute(vq_main_kernel,
                         cudaFuncAttributeMaxDynamicSharedMemorySize, SMEM_TOTAL);

    prep_kernel<<<NUM_CODES / 8, 256>>>(cb);
    vq_main_kernel<<<NBLOCKS, TPB, SMEM_TOTAL>>>(z, cb, out, loss_out);
}

// round 14
// speedup vs baseline: 2.2889x; 1.2630x over previous
#include <cuda_runtime.h>
#include <cuda_bf16.h>
#include <cstdint>

// VectorQuantizer R13: bf16 mma two-sweep filter with the CODE dimension
// split across warp pairs (2x warp parallelism: 4096 warps), B fragments
// read via LDG (L1-resident 128 KB) so smem/CTA ~23 KB -> multiple CTAs/SM,
// cn dropped from the filter proxy (bound folded into EPS2). Exact fp32
// recheck byte-identical to the R2 passer.

#define NUM_CODES 1024
#define DIM       64
#define HW        1024
#define N_VEC     32768
#define N_TOTAL   2097152
#define TPB       256          // 8 warps = 4 row-groups x 2 code-halves
#define VPB       64           // vectors per CTA
#define NBLOCKS   512
#define EPS2      1.6e-3f      // >= 2*(bf16 err 6.8e-4 + cn_max 6.1e-5)
#define INF       3.402823466e38f
#define ZPAD      65           // z row stride (f32): conflict-free LDS

// smem layout (bytes)
#define OFF_Z     0            // 64 rows x 65 f32 = 16640
#define OFF_CN    16640        // 1024 f32         = 4096
#define OFF_RM    20736        // 128 f32 (row x half row-min)
#define OFF_BST   21248        // 128 f32 (row x half best)
#define OFF_BSK   21760        // 128 i32 (row x half best k)
#define OFF_RED   22272        // 256 f32
#define SMEM_TOTAL 23296

__device__ float        g_cnorm[NUM_CODES];
__device__ float        g_partial[NBLOCKS];
__device__ __align__(16) uint4 g_bfrag[NUM_CODES * 8];  // 128 KB bf16 B frags
__device__ unsigned int g_done;

__device__ __forceinline__ uint32_t pk_bf2(float lo, float hi) {
    uint32_t u;
    asm("cvt.rn.bf16x2.f32 %0, %1, %2;" : "=r"(u) : "f"(hi), "f"(lo));
    return u;
}
__device__ __forceinline__ void mma_bf16(float* d, const uint32_t* a,
                                         uint32_t b0, uint32_t b1) {
    asm("mma.sync.aligned.m16n8k16.row.col.f32.bf16.bf16.f32 "
        "{%0,%1,%2,%3}, {%4,%5,%6,%7}, {%8,%9}, {%0,%1,%2,%3};"
        : "+f"(d[0]), "+f"(d[1]), "+f"(d[2]), "+f"(d[3])
        : "r"(a[0]), "r"(a[1]), "r"(a[2]), "r"(a[3]), "r"(b0), "r"(b1));
}

// exact fp32 score, byte-identical sequence to the round-2 passing kernel
__device__ __forceinline__ float exact_score(const float* __restrict__ cb, int k,
                                             const float* zrow, float zn, float cn) {
    const float4* row = (const float4*)(cb + (size_t)k * DIM);
    float d = 0.0f;
#pragma unroll 4
    for (int i = 0; i < 16; i++) {
        float4 a = row[i];
        d = fmaf(a.x, zrow[4 * i + 0], d);
        d = fmaf(a.y, zrow[4 * i + 1], d);
        d = fmaf(a.z, zrow[4 * i + 2], d);
        d = fmaf(a.w, zrow[4 * i + 3], d);
    }
    return __fadd_rn(__fsub_rn(zn, __fmul_rn(2.0f, d)), cn);
}

// ---------------------------------------------------------------------------
// Prep: warp per code — cn + 8 paired-kstep uint4 B-fragment slots
// (layout validated in R11/R12).
// ---------------------------------------------------------------------------
__global__ void prep_kernel(const float* __restrict__ cb) {
    int k = (blockIdx.x * blockDim.x + threadIdx.x) >> 5;
    int l = threadIdx.x & 31;
    if (k >= NUM_CODES) return;
    const float* row = cb + (size_t)k * DIM;
    float2 v = *(const float2*)(row + 2 * l);
    float cn = fmaf(v.x, v.x, v.y * v.y);
#pragma unroll
    for (int off = 16; off; off >>= 1)
        cn += __shfl_xor_sync(0xFFFFFFFFu, cn, off);
    if (l == 0) g_cnorm[k] = cn;

    if (l < 8) {
        int h = l >> 2, t = l & 3;
        int g = k >> 3, n = k & 7;
        int kkA = 2 * h, kkB = 2 * h + 1;
        uint4 val;
        val.x = pk_bf2(row[16 * kkA + 2 * t],     row[16 * kkA + 2 * t + 1]);
        val.y = pk_bf2(row[16 * kkA + 2 * t + 8], row[16 * kkA + 2 * t + 9]);
        val.z = pk_bf2(row[16 * kkB + 2 * t],     row[16 * kkB + 2 * t + 1]);
        val.w = pk_bf2(row[16 * kkB + 2 * t + 8], row[16 * kkB + 2 * t + 9]);
        g_bfrag[(g * 2 + h) * 32 + n * 4 + t] = val;
    }
}

// ---------------------------------------------------------------------------
// Main
// ---------------------------------------------------------------------------
__global__ void __launch_bounds__(TPB, 4)
vq_main_kernel(const float* __restrict__ z,
               const float* __restrict__ cb,
               float* __restrict__ out,
               float* __restrict__ loss_out) {
    extern __shared__ __align__(16) unsigned char smem[];
    float* s_z   = (float*)(smem + OFF_Z);
    float* s_cn  = (float*)(smem + OFF_CN);
    float* s_rm  = (float*)(smem + OFF_RM);
    float* s_bst = (float*)(smem + OFF_BST);
    int*   s_bsk = (int*)(smem + OFF_BSK);
    float* s_red = (float*)(smem + OFF_RED);

    const int tid  = threadIdx.x;
    const int w    = tid >> 5, lane = tid & 31;
    const int gid  = lane >> 2, tig = lane & 3;
    const int rg   = w >> 1;          // row group 0..3 (16 rows each)
    const int hc   = w & 1;           // codebook half 0/1

    // Stage cn (4/thread) + z (4 threads/vector, 16 dims each).
#pragma unroll
    for (int i = 0; i < 4; i++) s_cn[tid + i * TPB] = g_cnorm[tid + i * TPB];
    {
        int vz = tid >> 2, q = tid & 3;
        int nz = blockIdx.x * VPB + vz;
        const float* zsrc = z + ((size_t)(nz >> 10) << 16) + (nz & (HW - 1));
        float* zdst = s_z + vz * ZPAD;
#pragma unroll
        for (int i = 0; i < 16; i++) {
            int c = q * 16 + i;
            zdst[c] = zsrc[(size_t)c << 10];
        }
    }
    __syncthreads();

    // Rows: rA = rg*16+gid, rB = rA+8.
    const int rA = rg * 16 + gid;
    const int rB = rA + 8;
    const float* zrA = s_z + rA * ZPAD;
    const float* zrB = s_z + rB * ZPAD;

    // A fragments (validated mapping), values -2z in bf16.
    uint32_t afr[4][4];
#pragma unroll
    for (int kk = 0; kk < 4; kk++) {
        int c0 = 16 * kk + 2 * tig;
        afr[kk][0] = pk_bf2(-2.0f * zrA[c0],     -2.0f * zrA[c0 + 1]);
        afr[kk][1] = pk_bf2(-2.0f * zrB[c0],     -2.0f * zrB[c0 + 1]);
        afr[kk][2] = pk_bf2(-2.0f * zrA[c0 + 8], -2.0f * zrA[c0 + 9]);
        afr[kk][3] = pk_bf2(-2.0f * zrB[c0 + 8], -2.0f * zrB[c0 + 9]);
    }

    const int gbase = hc * 64;        // this warp's 64 groups (512 codes)

    // ---------------- Sweep 1: row minima of the raw mma proxy ------------
    float rmA = INF, rmB = INF;
#pragma unroll 4
    for (int gg = 0; gg < 64; gg++) {
        int g = gbase + gg;
        uint4 p0 = __ldg(&g_bfrag[(g * 2 + 0) * 32 + lane]);
        uint4 p1 = __ldg(&g_bfrag[(g * 2 + 1) * 32 + lane]);
        float d[4] = {0.f, 0.f, 0.f, 0.f};
        mma_bf16(d, afr[0], p0.x, p0.y);
        mma_bf16(d, afr[1], p0.z, p0.w);
        mma_bf16(d, afr[2], p1.x, p1.y);
        mma_bf16(d, afr[3], p1.z, p1.w);
        rmA = fminf(rmA, fminf(d[0], d[1]));
        rmB = fminf(rmB, fminf(d[2], d[3]));
    }
#pragma unroll
    for (int dlt = 1; dlt < 4; dlt <<= 1) {
        rmA = fminf(rmA, __shfl_xor_sync(0xFFFFFFFFu, rmA, dlt));
        rmB = fminf(rmB, __shfl_xor_sync(0xFFFFFFFFu, rmB, dlt));
    }
    if (tig == 0) {
        s_rm[rA * 2 + hc] = rmA;
        s_rm[rB * 2 + hc] = rmB;
    }
    __syncthreads();
    // FINAL per-row thresholds (min over both halves).
    const float thA = fminf(s_rm[rA * 2], s_rm[rA * 2 + 1]) + EPS2;
    const float thB = fminf(s_rm[rB * 2], s_rm[rB * 2 + 1]) + EPS2;

    // zn per row (reference sequential order; same smem bits both halves).
    float znA = 0.f, znB = 0.f;
#pragma unroll
    for (int c = 0; c < DIM; c++) znA = fmaf(zrA[c], zrA[c], znA);
#pragma unroll
    for (int c = 0; c < DIM; c++) znB = fmaf(zrB[c], zrB[c], znB);

    // -------- Sweep 2: per-row gated exact rescore vs FINAL thresholds ----
    float bA = INF, bB = INF;
    int   kA = 0x7FFFFFFF, kB = 0x7FFFFFFF;
#pragma unroll 2
    for (int gg = 0; gg < 64; gg++) {
        int g = gbase + gg;
        uint4 p0 = __ldg(&g_bfrag[(g * 2 + 0) * 32 + lane]);
        uint4 p1 = __ldg(&g_bfrag[(g * 2 + 1) * 32 + lane]);
        float d[4] = {0.f, 0.f, 0.f, 0.f};
        mma_bf16(d, afr[0], p0.x, p0.y);
        mma_bf16(d, afr[1], p0.z, p0.w);
        mma_bf16(d, afr[2], p1.x, p1.y);
        mma_bf16(d, afr[3], p1.z, p1.w);
        if ((fminf(d[0], d[1]) < thA) | (fminf(d[2], d[3]) < thB)) {  // rare
            int kb = g * 8 + 2 * tig;
            if (d[0] < thA) { float x = exact_score(cb, kb + 0, zrA, znA, s_cn[kb + 0]);
                              if (x < bA) { bA = x; kA = kb + 0; } }
            if (d[1] < thA) { float x = exact_score(cb, kb + 1, zrA, znA, s_cn[kb + 1]);
                              if (x < bA) { bA = x; kA = kb + 1; } }
            if (d[2] < thB) { float x = exact_score(cb, kb + 0, zrB, znB, s_cn[kb + 0]);
                              if (x < bB) { bB = x; kB = kb + 0; } }
            if (d[3] < thB) { float x = exact_score(cb, kb + 1, zrB, znB, s_cn[kb + 1]);
                              if (x < bB) { bB = x; kB = kb + 1; } }
        }
    }
    __syncwarp();

    // Merge across the 4 tig lanes; exact ties -> smaller k.
#pragma unroll
    for (int dlt = 1; dlt < 4; dlt <<= 1) {
        float ob; int ok;
        ob = __shfl_xor_sync(0xFFFFFFFFu, bA, dlt);
        ok = __shfl_xor_sync(0xFFFFFFFFu, kA, dlt);
        if (ob < bA || (ob == bA && ok < kA)) { bA = ob; kA = ok; }
        ob = __shfl_xor_sync(0xFFFFFFFFu, bB, dlt);
        ok = __shfl_xor_sync(0xFFFFFFFFu, kB, dlt);
        if (ob < bB || (ob == bB && ok < kB)) { bB = ob; kB = ok; }
    }
    if (tig == 0) {
        s_bst[rA * 2 + hc] = bA;  s_bsk[rA * 2 + hc] = kA;
        s_bst[rB * 2 + hc] = bB;  s_bsk[rB * 2 + hc] = kB;
    }
    __syncthreads();

    // Epilogue: 4 threads/vector, 16 dims each. Merge the two code-halves
    // (zn bits identical in both halves -> exact scores comparable; ties ->
    // smaller k = first index).
    const int vz = tid >> 2, q = tid & 3;
    const int nv = blockIdx.x * VPB + vz;
    float b0 = s_bst[vz * 2],  b1 = s_bst[vz * 2 + 1];
    int   h0 = s_bsk[vz * 2],  h1 = s_bsk[vz * 2 + 1];
    int bk = (b1 < b0 || (b1 == b0 && h1 < h0)) ? h1 : h0;
    if ((unsigned)bk >= NUM_CODES) bk = 0;   // defensive: never OOB
    const float* crow = cb + (size_t)bk * DIM;
    const float* zrow = s_z + vz * ZPAD;
    float* op = out + ((size_t)(nv >> 10) << 16) + (nv & (HW - 1));
    float lsum = 0.0f;
#pragma unroll
    for (int i = 0; i < 16; i++) {
        int c = q * 16 + i;
        float qv = crow[c];
        float zv = zrow[c];
        float dd = __fsub_rn(qv, zv);
        lsum = fmaf(dd, dd, lsum);
        op[(size_t)c << 10] = __fadd_rn(zv, dd);
    }

    // Deterministic block loss reduction.
    __syncthreads();
    s_red[tid] = lsum;
    __syncthreads();
#pragma unroll
    for (int st = TPB / 2; st > 0; st >>= 1) {
        if (tid < st) s_red[tid] += s_red[tid + st];
        __syncthreads();
    }
    if (tid == 0) g_partial[blockIdx.x] = s_red[0];

    // Fused finale: last CTA reduces all 512 partials in fixed order.
    if (loss_out) {
        __shared__ unsigned int s_rank;
        if (tid == 0) {
            __threadfence();
            s_rank = atomicAdd(&g_done, 1u);
        }
        __syncthreads();
        if (s_rank == NBLOCKS - 1) {
            __threadfence();
            s_red[tid] = g_partial[tid] + g_partial[tid + 256];
            __syncthreads();
#pragma unroll
            for (int st = 128; st > 0; st >>= 1) {
                if (tid < st) s_red[tid] += s_red[tid + st];
                __syncthreads();
            }
            if (tid == 0) {
                loss_out[0] = s_red[0] * (1.25f / (float)N_TOTAL);
                g_done = 0;   // reset for graph replay
            }
        }
    }
}

// ---------------------------------------------------------------------------
extern "C" void kernel_launch(void* const* d_in, const int* in_sizes, int n_in,
                              void* d_out, int out_size) {
    const float* z  = (const float*)d_in[0];
    const float* cb = (const float*)d_in[1];
    float* out = (float*)d_out;
    float* loss_out = (out_size > N_TOTAL) ? (out + (out_size - 1)) : nullptr;

    cudaFuncSetAttribute(vq_main_kernel,
                         cudaFuncAttributeMaxDynamicSharedMemorySize, SMEM_TOTAL);

    prep_kernel<<<NUM_CODES / 8, 256>>>(cb);
    vq_main_kernel<<<NBLOCKS, TPB, SMEM_TOTAL>>>(z, cb, out, loss_out);
}